// round 9
// baseline (speedup 1.0000x reference)
#include <cuda_runtime.h>
#include <cstdint>

#define BB  32
#define DD  128
#define CLN 1024
#define QLN 512

// ---------------- scratch (device globals; no allocations allowed) ----------
__device__ float g_Aeff[BB * CLN * DD];         // wq + wqc*C^T
__device__ float g_bias[BB * CLN];
__device__ float g_S[(size_t)BB * CLN * QLN];   // exp(S)  (B, CL, QL)
__device__ float g_rsum[BB * CLN];              // row sums (raw)
__device__ float g_csum[BB * QLN];              // col sums (raw)
__device__ float g_Tt[BB * DD * QLN];           // (S2^T C)^T  (B, D, QL)

// ---------------- permuted-smem fill helpers ----------------------------------
// Layout per 16-k chunk row (16 floats, 64B, no pad): float k stored at
//   slot = (k&3) ^ (row&3)   (16B slot),  pos = k>>2  (within slot)
// so slot s holds {k: k&3 == s'} = {s', s'+4, s'+8, s'+12} -> one LDS.128
// yields both kk-fragments. Slot-XOR makes fragment LDS conflict-free.

// load one float4 (row = t>>2 [+64 via t+256], 4 k-floats at j = t&3)
__device__ __forceinline__ void pload64(const float* __restrict__ g, int ld,
                                        int row0, int k0, int t, float4& v) {
    int r = t >> 2, j = t & 3;
    v = *(const float4*)(g + (size_t)(row0 + r) * ld + k0 + (j << 2));
}
__device__ __forceinline__ void pstore64(float* __restrict__ sm, int t, const float4& v) {
    int r = t >> 2, j = t & 3;
    float* p = sm + r * 16 + j;
    int s = (r & 3) << 2;
    p[s ^ 0]  = v.x;
    p[s ^ 4]  = v.y;
    p[s ^ 8]  = v.z;
    p[s ^ 12] = v.w;
}

// transposed fill: src [k][n] row-major; thread q = t&127, cs = (t>>7)*8
__device__ __forceinline__ void tload(const float* __restrict__ g, int ld,
                                      int n0, int k0, int t, float v[8]) {
    int q = t & 127, cs = (t >> 7) << 3;
#pragma unroll
    for (int i = 0; i < 8; ++i)
        v[i] = g[(size_t)(k0 + cs + i) * ld + n0 + q];
}
__device__ __forceinline__ void tstoreP(float* __restrict__ sm, int t, const float v[8]) {
    int q = t & 127, cs = (t >> 7) << 3;
    float* p = sm + q * 16;
    int sw = (q & 3) << 2;
#pragma unroll
    for (int i = 0; i < 8; ++i) {
        int k = cs + i;
        p[(((k & 3) << 2) ^ sw) + (k >> 2)] = v[i];
    }
}

// ---------------- mma.sync tf32 ----------------------------------------------
#define MMAF(D, A0, A1, A2, A3, B0, B1)                                            \
    asm volatile(                                                                  \
        "mma.sync.aligned.m16n8k8.row.col.f32.tf32.tf32.f32 "                      \
        "{%0,%1,%2,%3}, {%4,%5,%6,%7}, {%8,%9}, {%0,%1,%2,%3};"                    \
        : "+f"((D)[0]), "+f"((D)[1]), "+f"((D)[2]), "+f"((D)[3])                   \
        : "r"(__float_as_uint(A0)), "r"(__float_as_uint(A1)),                      \
          "r"(__float_as_uint(A2)), "r"(__float_as_uint(A3)),                      \
          "r"(__float_as_uint(B0)), "r"(__float_as_uint(B1)))

// 16-k chunk, warp tile 64x32 (4 mi x 4 ni), one B operand
__device__ __forceinline__ void mma_chunk4(const float* __restrict__ As,
                                           const float* __restrict__ Bs,
                                           float acc[4][4][4],
                                           int wm, int wn, int g, int tg) {
    int co = (tg ^ (g & 3)) << 2;
    float4 va0[4], va1[4], vb[4];
#pragma unroll
    for (int mi = 0; mi < 4; ++mi) {
        const float* p = As + (wm + (mi << 4) + g) * 16 + co;
        va0[mi] = *(const float4*)p;
        va1[mi] = *(const float4*)(p + 128);   // +8 rows
    }
#pragma unroll
    for (int ni = 0; ni < 4; ++ni)
        vb[ni] = *(const float4*)(Bs + (wn + (ni << 3) + g) * 16 + co);
#pragma unroll
    for (int mi = 0; mi < 4; ++mi)
#pragma unroll
        for (int ni = 0; ni < 4; ++ni) {
            MMAF(acc[mi][ni], va0[mi].x, va1[mi].x, va0[mi].y, va1[mi].y, vb[ni].x, vb[ni].y);
            MMAF(acc[mi][ni], va0[mi].z, va1[mi].z, va0[mi].w, va1[mi].w, vb[ni].z, vb[ni].w);
        }
}

// 16-k chunk, warp tile 32x32 per B (2 mi x 4 ni), two B operands share A
__device__ __forceinline__ void mma_chunk2d(const float* __restrict__ As,
                                            const float* __restrict__ B1,
                                            const float* __restrict__ B2,
                                            float ac1[2][4][4], float ac2[2][4][4],
                                            int wm, int wn, int g, int tg) {
    int co = (tg ^ (g & 3)) << 2;
    float4 va0[2], va1[2], v1[4], v2[4];
#pragma unroll
    for (int mi = 0; mi < 2; ++mi) {
        const float* p = As + (wm + (mi << 4) + g) * 16 + co;
        va0[mi] = *(const float4*)p;
        va1[mi] = *(const float4*)(p + 128);
    }
#pragma unroll
    for (int ni = 0; ni < 4; ++ni) {
        v1[ni] = *(const float4*)(B1 + (wn + (ni << 3) + g) * 16 + co);
        v2[ni] = *(const float4*)(B2 + (wn + (ni << 3) + g) * 16 + co);
    }
#pragma unroll
    for (int mi = 0; mi < 2; ++mi)
#pragma unroll
        for (int ni = 0; ni < 4; ++ni) {
            MMAF(ac1[mi][ni], va0[mi].x, va1[mi].x, va0[mi].y, va1[mi].y, v1[ni].x, v1[ni].y);
            MMAF(ac1[mi][ni], va0[mi].z, va1[mi].z, va0[mi].w, va1[mi].w, v1[ni].z, v1[ni].w);
            MMAF(ac2[mi][ni], va0[mi].x, va1[mi].x, va0[mi].y, va1[mi].y, v2[ni].x, v2[ni].y);
            MMAF(ac2[mi][ni], va0[mi].z, va1[mi].z, va0[mi].w, va1[mi].w, v2[ni].z, v2[ni].w);
        }
}

// ---------------- prepC: Aeff/bias + zero the sum buffers ---------------------
__global__ __launch_bounds__(256) void prepC_kernel(const float* __restrict__ C,
                                                    const float* __restrict__ W) {
    __shared__ float tile[128 * 68];
    int b = blockIdx.y, c0 = blockIdx.x << 6;
    int t = threadIdx.x, warp = t >> 5, lane = t & 31;
    int gi = (blockIdx.y * 16 + blockIdx.x) * 256 + t;
    if (gi < BB * CLN) g_rsum[gi] = 0.f;
    if (gi < BB * QLN) g_csum[gi] = 0.f;
#pragma unroll
    for (int i = 0; i < 8; ++i) {
        int idx = t + (i << 8);
        int d = idx >> 4, c4 = idx & 15;
        float4 v = *(const float4*)(C + ((size_t)b * DD + d) * CLN + c0 + (c4 << 2));
        *(float4*)(tile + d * 68 + (c4 << 2)) = v;
    }
    __syncthreads();
#pragma unroll
    for (int k = 0; k < 8; ++k) {
        int cc = (warp << 3) + k;
        size_t rc = (size_t)b * CLN + c0 + cc;
        const float* w = W + rc * (3 * DD);
        int d0 = lane << 2;
        float4 wq = *(const float4*)(w + d0);
        float4 wc = *(const float4*)(w + DD + d0);
        float4 wqc = *(const float4*)(w + 2 * DD + d0);
        float ct0 = tile[(d0 + 0) * 68 + cc];
        float ct1 = tile[(d0 + 1) * 68 + cc];
        float ct2 = tile[(d0 + 2) * 68 + cc];
        float ct3 = tile[(d0 + 3) * 68 + cc];
        float4 ae = make_float4(wq.x + wqc.x * ct0, wq.y + wqc.y * ct1,
                                wq.z + wqc.z * ct2, wq.w + wqc.w * ct3);
        *(float4*)(g_Aeff + (rc << 7) + d0) = ae;
        float v = wc.x * ct0 + wc.y * ct1 + wc.z * ct2 + wc.w * ct3;
#pragma unroll
        for (int o = 16; o; o >>= 1) v += __shfl_xor_sync(0xffffffffu, v, o);
        if (lane == 0) g_bias[rc] = v;
    }
}

// ---------------- G1: expS = exp(Aeff @ Q + bias); row/col sums via atomics ---
// M=128, N=128, K=128 (8 chunks); A native, B transposed from Q [d][q]
__global__ __launch_bounds__(256, 2) void g1_mma(const float* __restrict__ Qin) {
    __shared__ __align__(16) float sm[8192];   // A stages [0,2048)x2, B [4096,..)x2
    int b = blockIdx.z, n0 = blockIdx.x << 7, m0 = blockIdx.y << 7;
    const float* A = g_Aeff + (size_t)b * CLN * DD;
    const float* Qp = Qin + (size_t)b * DD * QLN;
    int t = threadIdx.x, lane = t & 31, warp = t >> 5;
    int g = lane >> 2, tg = lane & 3;
    int wm = (warp >> 2) << 6, wn = (warp & 3) << 5;
    float acc[4][4][4] = {};
    float* smA = sm;
    float* smB = sm + 4096;
    float4 va0, va1; float bv[8];
    pload64(A, DD, m0, 0, t, va0); pload64(A, DD, m0, 0, t + 256, va1);
    tload(Qp, QLN, n0, 0, t, bv);
    pstore64(smA, t, va0); pstore64(smA, t + 256, va1);
    tstoreP(smB, t, bv);
    __syncthreads();
    const int KT = 8;
    for (int i = 0; i < KT; ++i) {
        if (i + 1 < KT) {
            pload64(A, DD, m0, (i + 1) * 16, t, va0);
            pload64(A, DD, m0, (i + 1) * 16, t + 256, va1);
            tload(Qp, QLN, n0, (i + 1) * 16, t, bv);
        }
        mma_chunk4(smA + (i & 1) * 2048, smB + (i & 1) * 2048, acc, wm, wn, g, tg);
        if (i + 1 < KT) {
            int s = (i + 1) & 1;
            pstore64(smA + s * 2048, t, va0); pstore64(smA + s * 2048, t + 256, va1);
            tstoreP(smB + s * 2048, t, bv);
        }
        __syncthreads();
    }
    const float* bp = g_bias + b * CLN + m0;
#pragma unroll
    for (int mi = 0; mi < 4; ++mi)
#pragma unroll
        for (int h = 0; h < 2; ++h) {
            float bbv = bp[wm + (mi << 4) + g + (h << 3)];
#pragma unroll
            for (int ni = 0; ni < 4; ++ni) {
                acc[mi][ni][2 * h] = __expf(acc[mi][ni][2 * h] + bbv);
                acc[mi][ni][2 * h + 1] = __expf(acc[mi][ni][2 * h + 1] + bbv);
            }
        }
    float* Sp = g_S + (size_t)b * CLN * QLN;
#pragma unroll
    for (int mi = 0; mi < 4; ++mi)
#pragma unroll
        for (int h = 0; h < 2; ++h) {
            int row = m0 + wm + (mi << 4) + g + (h << 3);
#pragma unroll
            for (int ni = 0; ni < 4; ++ni) {
                int col = n0 + wn + (ni << 3) + (tg << 1);
                *(float2*)(Sp + (size_t)row * QLN + col) =
                    make_float2(acc[mi][ni][2 * h], acc[mi][ni][2 * h + 1]);
            }
        }
    {   // row sums (reduce over tg lanes)
        float rs[4][2];
#pragma unroll
        for (int mi = 0; mi < 4; ++mi)
#pragma unroll
            for (int h = 0; h < 2; ++h) {
                float s = 0.f;
#pragma unroll
                for (int ni = 0; ni < 4; ++ni) s += acc[mi][ni][2 * h] + acc[mi][ni][2 * h + 1];
                rs[mi][h] = s;
            }
#pragma unroll
        for (int o = 1; o <= 2; o <<= 1)
#pragma unroll
            for (int mi = 0; mi < 4; ++mi)
#pragma unroll
                for (int h = 0; h < 2; ++h)
                    rs[mi][h] += __shfl_xor_sync(0xffffffffu, rs[mi][h], o);
        if (tg == 0) {
            float* rp = g_rsum + b * CLN + m0;
#pragma unroll
            for (int mi = 0; mi < 4; ++mi)
#pragma unroll
                for (int h = 0; h < 2; ++h)
                    atomicAdd(rp + wm + (mi << 4) + g + (h << 3), rs[mi][h]);
        }
    }
    {   // col sums (reduce over g lanes)
        float cs[4][2];
#pragma unroll
        for (int ni = 0; ni < 4; ++ni)
#pragma unroll
            for (int p = 0; p < 2; ++p) {
                float s = 0.f;
#pragma unroll
                for (int mi = 0; mi < 4; ++mi) s += acc[mi][ni][p] + acc[mi][ni][2 + p];
                cs[ni][p] = s;
            }
#pragma unroll
        for (int o = 4; o <= 16; o <<= 1)
#pragma unroll
            for (int ni = 0; ni < 4; ++ni)
#pragma unroll
                for (int p = 0; p < 2; ++p)
                    cs[ni][p] += __shfl_xor_sync(0xffffffffu, cs[ni][p], o);
        if (g == 0) {
            float* cp = g_csum + b * QLN + n0;
#pragma unroll
            for (int ni = 0; ni < 4; ++ni)
#pragma unroll
                for (int p = 0; p < 2; ++p)
                    atomicAdd(cp + wn + (ni << 3) + (tg << 1) + p, cs[ni][p]);
        }
    }
}

// ---------------- G3: Tt[d][q] = (sum_c C[d][c] expS[c][q]) / csum[q] ---------
// M=D=128, N=128 (q-block), K=1024 (64 chunks); A=C native, B transposed expS
__global__ __launch_bounds__(256, 2) void g3_mma(const float* __restrict__ Cin) {
    __shared__ __align__(16) float sm[8192];
    int b = blockIdx.y, n0 = blockIdx.x << 7;
    const float* Ap = Cin + (size_t)b * DD * CLN;
    const float* Ep = g_S + (size_t)b * CLN * QLN;
    int t = threadIdx.x, lane = t & 31, warp = t >> 5;
    int g = lane >> 2, tg = lane & 3;
    int wm = (warp >> 2) << 6, wn = (warp & 3) << 5;
    float acc[4][4][4] = {};
    float* smA = sm;
    float* smB = sm + 4096;
    float4 va0, va1; float bv[8];
    pload64(Ap, CLN, 0, 0, t, va0); pload64(Ap, CLN, 0, 0, t + 256, va1);
    tload(Ep, QLN, n0, 0, t, bv);
    pstore64(smA, t, va0); pstore64(smA, t + 256, va1);
    tstoreP(smB, t, bv);
    __syncthreads();
    const int KT = 64;
    for (int i = 0; i < KT; ++i) {
        if (i + 1 < KT) {
            pload64(Ap, CLN, 0, (i + 1) * 16, t, va0);
            pload64(Ap, CLN, 0, (i + 1) * 16, t + 256, va1);
            tload(Ep, QLN, n0, (i + 1) * 16, t, bv);
        }
        mma_chunk4(smA + (i & 1) * 2048, smB + (i & 1) * 2048, acc, wm, wn, g, tg);
        if (i + 1 < KT) {
            int s = (i + 1) & 1;
            pstore64(smA + s * 2048, t, va0); pstore64(smA + s * 2048, t + 256, va1);
            tstoreP(smB + s * 2048, t, bv);
        }
        __syncthreads();
    }
    float* Ttp = g_Tt + (size_t)b * DD * QLN;
    const float* ci = g_csum + b * QLN + n0;
    float r0[4], r1[4];
#pragma unroll
    for (int ni = 0; ni < 4; ++ni) {
        int col = wn + (ni << 3) + (tg << 1);
        r0[ni] = 1.f / ci[col];
        r1[ni] = 1.f / ci[col + 1];
    }
#pragma unroll
    for (int mi = 0; mi < 4; ++mi)
#pragma unroll
        for (int h = 0; h < 2; ++h) {
            int d = wm + (mi << 4) + g + (h << 3);
#pragma unroll
            for (int ni = 0; ni < 4; ++ni) {
                int col = wn + (ni << 3) + (tg << 1);
                float2 v = make_float2(acc[mi][ni][2 * h] * r0[ni],
                                       acc[mi][ni][2 * h + 1] * r1[ni]);
                *(float2*)(Ttp + (size_t)d * QLN + n0 + col) = v;
            }
        }
}

// ---------------- G24 fused: all four output blocks ---------------------------
// M=64 (CL), N=128 (D), K=512 (32 chunks); A=expS (shared), B1=Q, B2=Tt, all native
__global__ __launch_bounds__(256, 2) void g24_mma(const float* __restrict__ Qin,
                                                  const float* __restrict__ Cin,
                                                  float* __restrict__ out) {
    __shared__ __align__(16) float sm[10240];  // A [0,2048)x2s, B1 [2048,6144), B2 [6144,10240)
    int b = blockIdx.y, m0 = blockIdx.x << 6;
    const float* A = g_S + (size_t)b * CLN * QLN;
    const float* B1 = Qin + (size_t)b * DD * QLN;
    const float* B2 = g_Tt + (size_t)b * DD * QLN;
    int t = threadIdx.x, lane = t & 31, warp = t >> 5;
    int g = lane >> 2, tg = lane & 3;
    int wm = (warp >> 2) << 5, wn = (warp & 3) << 5;
    float ac1[2][4][4] = {}, ac2[2][4][4] = {};
    float* smA = sm;
    float* smB1 = sm + 2048;
    float* smB2 = sm + 6144;
    float4 va, vb10, vb11, vb20, vb21;
    pload64(A, QLN, m0, 0, t, va);
    pload64(B1, QLN, 0, 0, t, vb10); pload64(B1, QLN, 0, 0, t + 256, vb11);
    pload64(B2, QLN, 0, 0, t, vb20); pload64(B2, QLN, 0, 0, t + 256, vb21);
    pstore64(smA, t, va);
    pstore64(smB1, t, vb10); pstore64(smB1, t + 256, vb11);
    pstore64(smB2, t, vb20); pstore64(smB2, t + 256, vb21);
    __syncthreads();
    const int KT = 32;
    for (int i = 0; i < KT; ++i) {
        if (i + 1 < KT) {
            pload64(A, QLN, m0, (i + 1) * 16, t, va);
            pload64(B1, QLN, 0, (i + 1) * 16, t, vb10);
            pload64(B1, QLN, 0, (i + 1) * 16, t + 256, vb11);
            pload64(B2, QLN, 0, (i + 1) * 16, t, vb20);
            pload64(B2, QLN, 0, (i + 1) * 16, t + 256, vb21);
        }
        mma_chunk2d(smA + (i & 1) * 1024, smB1 + (i & 1) * 2048, smB2 + (i & 1) * 2048,
                    ac1, ac2, wm, wn, g, tg);
        if (i + 1 < KT) {
            int s = (i + 1) & 1;
            pstore64(smA + s * 1024, t, va);
            pstore64(smB1 + s * 2048, t, vb10); pstore64(smB1 + s * 2048, t + 256, vb11);
            pstore64(smB2 + s * 2048, t, vb20); pstore64(smB2 + s * 2048, t + 256, vb21);
        }
        __syncthreads();
    }
    // epilogue: stage both outputs per 32-row chunk, write 4 output blocks
    const float* rp = g_rsum + b * CLN;
    size_t ob = (size_t)b * (4 * DD) * CLN;
    float* smX = sm;            // 32 x 133
    float* smY = sm + 4256;     // 32 x 133
    for (int ch = 0; ch < 2; ++ch) {
        __syncthreads();
        if ((warp >> 2) == ch) {
#pragma unroll
            for (int mi = 0; mi < 2; ++mi)
#pragma unroll
                for (int h = 0; h < 2; ++h) {
                    int ml = (mi << 4) + g + (h << 3);
                    int row = m0 + wm + (mi << 4) + g + (h << 3);
                    float sc = 1.f / rp[row];
#pragma unroll
                    for (int ni = 0; ni < 4; ++ni) {
                        int n = wn + (ni << 3) + (tg << 1);
                        smX[ml * 133 + n] = ac1[mi][ni][2 * h] * sc;
                        smX[ml * 133 + n + 1] = ac1[mi][ni][2 * h + 1] * sc;
                        smY[ml * 133 + n] = ac2[mi][ni][2 * h] * sc;
                        smY[ml * 133 + n + 1] = ac2[mi][ni][2 * h + 1] * sc;
                    }
                }
        }
        __syncthreads();
        int cl = t & 31, dw = t >> 5;
        int c = m0 + (ch << 5) + cl;
#pragma unroll
        for (int i = 0; i < 16; ++i) {
            int d = dw + (i << 3);
            float v1 = smX[cl * 133 + d];
            float v2 = smY[cl * 133 + d];
            float cv = Cin[((size_t)b * DD + d) * CLN + c];
            out[ob + (size_t)d * CLN + c] = cv;
            out[ob + (size_t)(DD + d) * CLN + c] = v1;
            out[ob + (size_t)(2 * DD + d) * CLN + c] = cv * v1;
            out[ob + (size_t)(3 * DD + d) * CLN + c] = cv * v2;
        }
    }
}

// ---------------- launch ------------------------------------------------------
extern "C" void kernel_launch(void* const* d_in, const int* in_sizes, int n_in,
                              void* d_out, int out_size) {
    const float* C = (const float*)d_in[0];
    const float* Q = (const float*)d_in[1];
    const float* W = (const float*)d_in[2];
    float* out = (float*)d_out;

    prepC_kernel<<<dim3(CLN / 64, BB), 256>>>(C, W);
    g1_mma<<<dim3(QLN / 128, CLN / 128, BB), 256>>>(Q);
    g3_mma<<<dim3(QLN / 128, BB), 256>>>(C);
    g24_mma<<<dim3(CLN / 64, BB), 256>>>(Q, C, out);
}

// round 10
// speedup vs baseline: 1.4020x; 1.4020x over previous
#include <cuda_runtime.h>
#include <cstdint>

#define BB  32
#define DD  128
#define CLN 1024
#define QLN 512

// ---------------- scratch (device globals; no allocations allowed) ----------
__device__ float g_Aeff[BB * CLN * DD];         // wq + wqc*C^T
__device__ float g_bias[BB * CLN];
__device__ float g_S[(size_t)BB * CLN * QLN];   // exp(S)  (B, CL, QL)
__device__ float g_rsum[BB * CLN];              // row sums (raw)
__device__ float g_csum[BB * QLN];              // col sums (raw)
__device__ float g_Tt[BB * DD * QLN];           // (S2^T C)^T  (B, D, QL)

// ---------------- helpers -----------------------------------------------------
__device__ __forceinline__ uint32_t s2u(const void* p) {
    uint32_t a;
    asm("{ .reg .u64 t; cvta.to.shared.u64 t, %1; cvt.u32.u64 %0, t; }" : "=r"(a) : "l"(p));
    return a;
}
#define CPC()  asm volatile("cp.async.commit_group;" ::: "memory")
#define CPW0() asm volatile("cp.async.wait_group 0;" ::: "memory")
#define CPW1() asm volatile("cp.async.wait_group 1;" ::: "memory")

// cp.async fill: 128 rows x 16 floats, row stride 20 floats
__device__ __forceinline__ void cfill(uint32_t sb, const float* __restrict__ g,
                                      int ld, int row0, int k0, int t) {
#pragma unroll
    for (int j = 0; j < 2; ++j) {
        int lin = t + (j << 8);
        int r = lin >> 2, q = lin & 3;
        asm volatile("cp.async.cg.shared.global [%0], [%1], 16;"
                     :: "r"(sb + r * 80 + q * 16),
                        "l"(g + (size_t)(row0 + r) * ld + k0 + (q << 2)));
    }
}
// 64-row variant (one float4 per thread)
__device__ __forceinline__ void cfill64(uint32_t sb, const float* __restrict__ g,
                                        int ld, int row0, int k0, int t) {
    int r = t >> 2, q = t & 3;
    asm volatile("cp.async.cg.shared.global [%0], [%1], 16;"
                 :: "r"(sb + r * 80 + q * 16),
                    "l"(g + (size_t)(row0 + r) * ld + k0 + (q << 2)));
}
// transposed fill via 4B cp.async: src [k][n], dst smem [n][k] stride 20
__device__ __forceinline__ void cfillT(uint32_t sb, const float* __restrict__ g,
                                       int ld, int n0, int k0, int t) {
    int q = t & 127, cs = (t >> 7) << 3;
#pragma unroll
    for (int i = 0; i < 8; ++i)
        asm volatile("cp.async.ca.shared.global [%0], [%1], 4;"
                     :: "r"(sb + (q * 20 + cs + i) * 4),
                        "l"(g + (size_t)(k0 + cs + i) * ld + n0 + q));
}

// transposed fill (LDG part): src [k][n] row-major ld; chunk = 16 k-rows x 128 n
__device__ __forceinline__ void tload(const float* __restrict__ g, int ld,
                                      int n0, int k0, int t, float v[8]) {
    int q = t & 127, cs = (t >> 7) << 3;
#pragma unroll
    for (int i = 0; i < 8; ++i)
        v[i] = g[(size_t)(k0 + cs + i) * ld + n0 + q];
}
__device__ __forceinline__ void tstore(float* smf, int t, const float v[8]) {
    int q = t & 127, cs = (t >> 7) << 3;
#pragma unroll
    for (int i = 0; i < 8; ++i) smf[q * 20 + cs + i] = v[i];
}

// ---------------- mma.sync tf32 ----------------------------------------------
#define MMA_TF32(D, A, B)                                                          \
    asm volatile(                                                                  \
        "mma.sync.aligned.m16n8k8.row.col.f32.tf32.tf32.f32 "                      \
        "{%0,%1,%2,%3}, {%4,%5,%6,%7}, {%8,%9}, {%0,%1,%2,%3};"                    \
        : "+f"((D)[0]), "+f"((D)[1]), "+f"((D)[2]), "+f"((D)[3])                   \
        : "r"((A)[0]), "r"((A)[1]), "r"((A)[2]), "r"((A)[3]),                      \
          "r"((B)[0]), "r"((B)[1]))

__device__ __forceinline__ void mma_chunk(const float* __restrict__ As,
                                          const float* __restrict__ Bs,
                                          float acc[4][4][4],
                                          int wm, int wn, int g, int tg) {
#pragma unroll
    for (int kk = 0; kk < 2; ++kk) {
        int kc = (kk << 3) + tg;
        unsigned a[4][4], bf[4][2];
#pragma unroll
        for (int mi = 0; mi < 4; ++mi) {
            const float* p = As + (wm + (mi << 4) + g) * 20 + kc;
            a[mi][0] = __float_as_uint(p[0]);
            a[mi][1] = __float_as_uint(p[160]);
            a[mi][2] = __float_as_uint(p[4]);
            a[mi][3] = __float_as_uint(p[164]);
        }
#pragma unroll
        for (int ni = 0; ni < 4; ++ni) {
            const float* p = Bs + (wn + (ni << 3) + g) * 20 + kc;
            bf[ni][0] = __float_as_uint(p[0]);
            bf[ni][1] = __float_as_uint(p[4]);
        }
#pragma unroll
        for (int mi = 0; mi < 4; ++mi)
#pragma unroll
            for (int ni = 0; ni < 4; ++ni) MMA_TF32(acc[mi][ni], a[mi], bf[ni]);
    }
}

// fused variant: one A (2 mi), two B operands
__device__ __forceinline__ void mma_chunk2(const float* __restrict__ As,
                                           const float* __restrict__ Bs1,
                                           const float* __restrict__ Bs2,
                                           float ac1[2][4][4], float ac2[2][4][4],
                                           int wm, int wn, int g, int tg) {
#pragma unroll
    for (int kk = 0; kk < 2; ++kk) {
        int kc = (kk << 3) + tg;
        unsigned a[2][4], b1[4][2], b2[4][2];
#pragma unroll
        for (int mi = 0; mi < 2; ++mi) {
            const float* p = As + (wm + (mi << 4) + g) * 20 + kc;
            a[mi][0] = __float_as_uint(p[0]);
            a[mi][1] = __float_as_uint(p[160]);
            a[mi][2] = __float_as_uint(p[4]);
            a[mi][3] = __float_as_uint(p[164]);
        }
#pragma unroll
        for (int ni = 0; ni < 4; ++ni) {
            const float* p = Bs1 + (wn + (ni << 3) + g) * 20 + kc;
            b1[ni][0] = __float_as_uint(p[0]);
            b1[ni][1] = __float_as_uint(p[4]);
            const float* p2 = Bs2 + (wn + (ni << 3) + g) * 20 + kc;
            b2[ni][0] = __float_as_uint(p2[0]);
            b2[ni][1] = __float_as_uint(p2[4]);
        }
#pragma unroll
        for (int mi = 0; mi < 2; ++mi)
#pragma unroll
            for (int ni = 0; ni < 4; ++ni) {
                MMA_TF32(ac1[mi][ni], a[mi], b1[ni]);
                MMA_TF32(ac2[mi][ni], a[mi], b2[ni]);
            }
    }
}

// ---------------- prepC: Aeff/bias + zero the sum buffers ---------------------
__global__ __launch_bounds__(256) void prepC_kernel(const float* __restrict__ C,
                                                    const float* __restrict__ W) {
    __shared__ float tile[128 * 68];
    int b = blockIdx.y, c0 = blockIdx.x << 6;
    int t = threadIdx.x, warp = t >> 5, lane = t & 31;
    int gi = (blockIdx.y * 16 + blockIdx.x) * 256 + t;
    if (gi < BB * CLN) g_rsum[gi] = 0.f;
    if (gi < BB * QLN) g_csum[gi] = 0.f;
#pragma unroll
    for (int i = 0; i < 8; ++i) {
        int idx = t + (i << 8);
        int d = idx >> 4, c4 = idx & 15;
        float4 v = *(const float4*)(C + ((size_t)b * DD + d) * CLN + c0 + (c4 << 2));
        *(float4*)(tile + d * 68 + (c4 << 2)) = v;
    }
    __syncthreads();
#pragma unroll
    for (int k = 0; k < 8; ++k) {
        int cc = (warp << 3) + k;
        size_t rc = (size_t)b * CLN + c0 + cc;
        const float* w = W + rc * (3 * DD);
        int d0 = lane << 2;
        float4 wq = *(const float4*)(w + d0);
        float4 wc = *(const float4*)(w + DD + d0);
        float4 wqc = *(const float4*)(w + 2 * DD + d0);
        float ct0 = tile[(d0 + 0) * 68 + cc];
        float ct1 = tile[(d0 + 1) * 68 + cc];
        float ct2 = tile[(d0 + 2) * 68 + cc];
        float ct3 = tile[(d0 + 3) * 68 + cc];
        float4 ae = make_float4(wq.x + wqc.x * ct0, wq.y + wqc.y * ct1,
                                wq.z + wqc.z * ct2, wq.w + wqc.w * ct3);
        *(float4*)(g_Aeff + (rc << 7) + d0) = ae;
        float v = wc.x * ct0 + wc.y * ct1 + wc.z * ct2 + wc.w * ct3;
#pragma unroll
        for (int o = 16; o; o >>= 1) v += __shfl_xor_sync(0xffffffffu, v, o);
        if (lane == 0) g_bias[rc] = v;
    }
}

// ---------------- G1: expS = exp(Aeff @ Q + bias); row/col sums via atomics ---
__global__ __launch_bounds__(256) void g1_mma(const float* __restrict__ Qin) {
    __shared__ float sm[10240];
    int b = blockIdx.z, n0 = blockIdx.x << 7, m0 = blockIdx.y << 7;
    const float* A = g_Aeff + (size_t)b * CLN * DD;
    const float* Qp = Qin + (size_t)b * DD * QLN;
    uint32_t su = s2u(sm);
    int t = threadIdx.x, lane = t & 31, warp = t >> 5;
    int g = lane >> 2, tg = lane & 3;
    int wm = (warp >> 2) << 6, wn = (warp & 3) << 5;
    float acc[4][4][4] = {};
    const int KT = DD / 16;
    float bv[8];
    cfill(su, A, DD, m0, 0, t);
    tload(Qp, QLN, n0, 0, t, bv);
    tstore(sm + 5120, t, bv);
    CPC();
    for (int i = 0; i < KT; ++i) {
        if (i + 1 < KT) tload(Qp, QLN, n0, (i + 1) * 16, t, bv);
        CPW0();
        __syncthreads();
        if (i + 1 < KT) {
            int s = (i + 1) & 1;
            cfill(su + s * 10240, A, DD, m0, (i + 1) * 16, t);
            tstore(sm + 5120 + s * 2560, t, bv);
            CPC();
        }
        mma_chunk(sm + (i & 1) * 2560, sm + 5120 + (i & 1) * 2560, acc, wm, wn, g, tg);
    }
    const float* bp = g_bias + b * CLN + m0;
#pragma unroll
    for (int mi = 0; mi < 4; ++mi)
#pragma unroll
        for (int h = 0; h < 2; ++h) {
            float bbv = bp[wm + (mi << 4) + g + (h << 3)];
#pragma unroll
            for (int ni = 0; ni < 4; ++ni) {
                acc[mi][ni][2 * h] = __expf(acc[mi][ni][2 * h] + bbv);
                acc[mi][ni][2 * h + 1] = __expf(acc[mi][ni][2 * h + 1] + bbv);
            }
        }
    float* Sp = g_S + (size_t)b * CLN * QLN;
#pragma unroll
    for (int mi = 0; mi < 4; ++mi)
#pragma unroll
        for (int h = 0; h < 2; ++h) {
            int row = m0 + wm + (mi << 4) + g + (h << 3);
#pragma unroll
            for (int ni = 0; ni < 4; ++ni) {
                int col = n0 + wn + (ni << 3) + (tg << 1);
                *(float2*)(Sp + (size_t)row * QLN + col) =
                    make_float2(acc[mi][ni][2 * h], acc[mi][ni][2 * h + 1]);
            }
        }
    {   // row sums (reduce over tg lanes)
        float rs[4][2];
#pragma unroll
        for (int mi = 0; mi < 4; ++mi)
#pragma unroll
            for (int h = 0; h < 2; ++h) {
                float s = 0.f;
#pragma unroll
                for (int ni = 0; ni < 4; ++ni) s += acc[mi][ni][2 * h] + acc[mi][ni][2 * h + 1];
                rs[mi][h] = s;
            }
#pragma unroll
        for (int o = 1; o <= 2; o <<= 1)
#pragma unroll
            for (int mi = 0; mi < 4; ++mi)
#pragma unroll
                for (int h = 0; h < 2; ++h)
                    rs[mi][h] += __shfl_xor_sync(0xffffffffu, rs[mi][h], o);
        if (tg == 0) {
            float* rp = g_rsum + b * CLN + m0;
#pragma unroll
            for (int mi = 0; mi < 4; ++mi)
#pragma unroll
                for (int h = 0; h < 2; ++h)
                    atomicAdd(rp + wm + (mi << 4) + g + (h << 3), rs[mi][h]);
        }
    }
    {   // col sums (reduce over g lanes)
        float cs[4][2];
#pragma unroll
        for (int ni = 0; ni < 4; ++ni)
#pragma unroll
            for (int p = 0; p < 2; ++p) {
                float s = 0.f;
#pragma unroll
                for (int mi = 0; mi < 4; ++mi) s += acc[mi][ni][p] + acc[mi][ni][2 + p];
                cs[ni][p] = s;
            }
#pragma unroll
        for (int o = 4; o <= 16; o <<= 1)
#pragma unroll
            for (int ni = 0; ni < 4; ++ni)
#pragma unroll
                for (int p = 0; p < 2; ++p)
                    cs[ni][p] += __shfl_xor_sync(0xffffffffu, cs[ni][p], o);
        if (g == 0) {
            float* cp = g_csum + b * QLN + n0;
#pragma unroll
            for (int ni = 0; ni < 4; ++ni)
#pragma unroll
                for (int p = 0; p < 2; ++p)
                    atomicAdd(cp + wn + (ni << 3) + (tg << 1) + p, cs[ni][p]);
        }
    }
}

// ---------------- G3: Tt[d][q] = (sum_c C[d][c] expS[c][q]) / csum[q] ---------
// 3-stage cp.async pipeline; A stages [0,7680) fl, B stages [7680,15360) fl
__global__ __launch_bounds__(256) void g3_mma(const float* __restrict__ Cin) {
    extern __shared__ float sm[];
    int b = blockIdx.y, n0 = blockIdx.x << 7;
    const float* Ap = Cin + (size_t)b * DD * CLN;
    const float* Ep = g_S + (size_t)b * CLN * QLN;
    uint32_t su = s2u(sm);
    int t = threadIdx.x, lane = t & 31, warp = t >> 5;
    int g = lane >> 2, tg = lane & 3;
    int wm = (warp >> 2) << 6, wn = (warp & 3) << 5;
    float acc[4][4][4] = {};
    const int KT = CLN / 16;
    cfill(su, Ap, CLN, 0, 0, t);
    cfillT(su + 30720, Ep, QLN, n0, 0, t);
    CPC();
    cfill(su + 10240, Ap, CLN, 0, 16, t);
    cfillT(su + 40960, Ep, QLN, n0, 16, t);
    CPC();
    for (int i = 0; i < KT; ++i) {
        if (i + 1 < KT) CPW1(); else CPW0();
        __syncthreads();
        if (i + 2 < KT) {
            int s = (i + 2) % 3;
            cfill(su + s * 10240, Ap, CLN, 0, (i + 2) * 16, t);
            cfillT(su + 30720 + s * 10240, Ep, QLN, n0, (i + 2) * 16, t);
            CPC();
        }
        int s = i % 3;
        mma_chunk(sm + s * 2560, sm + 7680 + s * 2560, acc, wm, wn, g, tg);
    }
    float* Ttp = g_Tt + (size_t)b * DD * QLN;
    const float* ci = g_csum + b * QLN + n0;
    float r0[4], r1[4];
#pragma unroll
    for (int ni = 0; ni < 4; ++ni) {
        int col = wn + (ni << 3) + (tg << 1);
        r0[ni] = 1.f / ci[col];
        r1[ni] = 1.f / ci[col + 1];
    }
#pragma unroll
    for (int mi = 0; mi < 4; ++mi)
#pragma unroll
        for (int h = 0; h < 2; ++h) {
            int d = wm + (mi << 4) + g + (h << 3);
#pragma unroll
            for (int ni = 0; ni < 4; ++ni) {
                int col = wn + (ni << 3) + (tg << 1);
                float2 v = make_float2(acc[mi][ni][2 * h] * r0[ni],
                                       acc[mi][ni][2 * h + 1] * r1[ni]);
                *(float2*)(Ttp + (size_t)d * QLN + n0 + col) = v;
            }
        }
}

// ---------------- G24 fused: all four output blocks ---------------------------
// 3-stage cp.async; A stages [0,3840) fl, B1 [3840,11520), B2 [11520,19200)
__global__ __launch_bounds__(256) void g24_mma(const float* __restrict__ Qin,
                                               const float* __restrict__ Cin,
                                               float* __restrict__ out) {
    extern __shared__ float sm[];
    int b = blockIdx.y, m0 = blockIdx.x << 6;
    const float* A = g_S + (size_t)b * CLN * QLN;
    const float* B1 = Qin + (size_t)b * DD * QLN;
    const float* B2 = g_Tt + (size_t)b * DD * QLN;
    uint32_t su = s2u(sm);
    int t = threadIdx.x, lane = t & 31, warp = t >> 5;
    int g = lane >> 2, tg = lane & 3;
    int wm = (warp >> 2) << 5, wn = (warp & 3) << 5;
    float ac1[2][4][4] = {}, ac2[2][4][4] = {};
    const int KT = QLN / 16;
    cfill64(su, A, QLN, m0, 0, t);
    cfill(su + 15360, B1, QLN, 0, 0, t);
    cfill(su + 46080, B2, QLN, 0, 0, t);
    CPC();
    cfill64(su + 5120, A, QLN, m0, 16, t);
    cfill(su + 15360 + 10240, B1, QLN, 0, 16, t);
    cfill(su + 46080 + 10240, B2, QLN, 0, 16, t);
    CPC();
    for (int i = 0; i < KT; ++i) {
        if (i + 1 < KT) CPW1(); else CPW0();
        __syncthreads();
        if (i + 2 < KT) {
            int s = (i + 2) % 3;
            cfill64(su + s * 5120, A, QLN, m0, (i + 2) * 16, t);
            cfill(su + 15360 + s * 10240, B1, QLN, 0, (i + 2) * 16, t);
            cfill(su + 46080 + s * 10240, B2, QLN, 0, (i + 2) * 16, t);
            CPC();
        }
        int s = i % 3;
        mma_chunk2(sm + s * 1280, sm + 3840 + s * 2560, sm + 11520 + s * 2560,
                   ac1, ac2, wm, wn, g, tg);
    }
    // epilogue: stage both outputs per 32-row chunk, write 4 output blocks
    const float* rp = g_rsum + b * CLN;
    size_t ob = (size_t)b * (4 * DD) * CLN;
    float* smX = sm;            // 32 x 133
    float* smY = sm + 4256;     // 32 x 133
    for (int ch = 0; ch < 2; ++ch) {
        __syncthreads();
        if ((warp >> 2) == ch) {
#pragma unroll
            for (int mi = 0; mi < 2; ++mi)
#pragma unroll
                for (int h = 0; h < 2; ++h) {
                    int ml = (mi << 4) + g + (h << 3);
                    int row = m0 + wm + (mi << 4) + g + (h << 3);
                    float sc = 1.f / rp[row];
#pragma unroll
                    for (int ni = 0; ni < 4; ++ni) {
                        int n = wn + (ni << 3) + (tg << 1);
                        smX[ml * 133 + n] = ac1[mi][ni][2 * h] * sc;
                        smX[ml * 133 + n + 1] = ac1[mi][ni][2 * h + 1] * sc;
                        smY[ml * 133 + n] = ac2[mi][ni][2 * h] * sc;
                        smY[ml * 133 + n + 1] = ac2[mi][ni][2 * h + 1] * sc;
                    }
                }
        }
        __syncthreads();
        int cl = t & 31, dw = t >> 5;
        int c = m0 + (ch << 5) + cl;
#pragma unroll
        for (int i = 0; i < 16; ++i) {
            int d = dw + (i << 3);
            float v1 = smX[cl * 133 + d];
            float v2 = smY[cl * 133 + d];
            float cv = Cin[((size_t)b * DD + d) * CLN + c];
            out[ob + (size_t)d * CLN + c] = cv;
            out[ob + (size_t)(DD + d) * CLN + c] = v1;
            out[ob + (size_t)(2 * DD + d) * CLN + c] = cv * v1;
            out[ob + (size_t)(3 * DD + d) * CLN + c] = cv * v2;
        }
    }
}

// ---------------- launch ------------------------------------------------------
extern "C" void kernel_launch(void* const* d_in, const int* in_sizes, int n_in,
                              void* d_out, int out_size) {
    const float* C = (const float*)d_in[0];
    const float* Q = (const float*)d_in[1];
    const float* W = (const float*)d_in[2];
    float* out = (float*)d_out;

    const int SM3 = 61440;    // g3: 3 x (2560 A + 2560 B) floats
    const int SM24 = 76800;   // g24: 3 x (1280 A + 2560 B1 + 2560 B2) floats
    cudaFuncSetAttribute(g3_mma, cudaFuncAttributeMaxDynamicSharedMemorySize, SM3);
    cudaFuncSetAttribute(g24_mma, cudaFuncAttributeMaxDynamicSharedMemorySize, SM24);

    prepC_kernel<<<dim3(CLN / 64, BB), 256>>>(C, W);
    g1_mma<<<dim3(QLN / 128, CLN / 128, BB), 256>>>(Q);
    g3_mma<<<dim3(QLN / 128, BB), 256, SM3>>>(C);
    g24_mma<<<dim3(CLN / 64, BB), 256, SM24>>>(Q, C, out);
}